// round 4
// baseline (speedup 1.0000x reference)
#include <cuda_runtime.h>
#include <math.h>
#include <stdint.h>

#define NROWS 12288          // B*T
#define TT    1536
#define DD    512
#define NH    8
#define HDIM  64

// ---------------- scratch (device globals; no allocations allowed) ----------
__device__ float g_h[NROWS * DD];        // conv intermediate
__device__ float g_x[NROWS * DD];        // residual stream
__device__ float g_y[NROWS * DD];        // LN output
__device__ float g_qkv[NROWS * 3 * DD];
__device__ float g_attn[NROWS * DD];
__device__ float g_ffn[NROWS * 4 * DD];

__device__ __forceinline__ float to_tf32(float x) {
    float r;
    asm("cvt.rna.tf32.f32 %0, %1;" : "=f"(r) : "f"(x));
    return r;
}
__device__ __forceinline__ float gelu_f(float v) {
    return 0.5f * v * (1.0f + erff(v * 0.7071067811865476f));
}
__device__ __forceinline__ unsigned smem_u32(const void* p) {
    return (unsigned)__cvta_generic_to_shared(p);
}
__device__ __forceinline__ void cp_async16(void* dst, const void* src) {
    asm volatile("cp.async.ca.shared.global [%0], [%1], 16;\n"
                 :: "r"(smem_u32(dst)), "l"(src));
}
__device__ __forceinline__ void cp_commit() {
    asm volatile("cp.async.commit_group;\n");
}
template <int N>
__device__ __forceinline__ void cp_wait() {
    asm volatile("cp.async.wait_group %0;\n" :: "n"(N));
}

// ---------------- depthwise conv k=5, pad=2 ---------------------------------
__global__ void conv_dw_kernel(const float* __restrict__ x,
                               const float* __restrict__ dww,
                               const float* __restrict__ dwb,
                               float* __restrict__ h) {
    int idx = blockIdx.x * blockDim.x + threadIdx.x;   // over NROWS*128
    int row = idx >> 7;
    int c   = (idx & 127) << 2;
    int b = row / TT, t = row - b * TT;
    float4 acc = *(const float4*)(dwb + c);
#pragma unroll
    for (int w = 0; w < 5; w++) {
        int tt = t + w - 2;
        if (tt >= 0 && tt < TT) {
            float4 xv = *(const float4*)(x + ((size_t)(b * TT + tt)) * DD + c);
            float4 kv = *(const float4*)(dww + w * DD + c);
            acc.x += xv.x * kv.x; acc.y += xv.y * kv.y;
            acc.z += xv.z * kv.z; acc.w += xv.w * kv.w;
        }
    }
    *(float4*)(h + (size_t)row * DD + c) = acc;
}

// ---------------- layernorm (1 block / row, 128 thr, float4) ----------------
__global__ void ln_kernel(const float* __restrict__ x,
                          const float* __restrict__ w,
                          const float* __restrict__ bb,
                          float* __restrict__ y) {
    int row = blockIdx.x;
    int t = threadIdx.x;                 // 128 threads
    float4 v = ((const float4*)(x + (size_t)row * DD))[t];
    float s = v.x + v.y + v.z + v.w;
    float q = v.x * v.x + v.y * v.y + v.z * v.z + v.w * v.w;
#pragma unroll
    for (int o = 16; o > 0; o >>= 1) {
        s += __shfl_xor_sync(0xffffffffu, s, o);
        q += __shfl_xor_sync(0xffffffffu, q, o);
    }
    __shared__ float ss[4], sq[4];
    __shared__ float smean, srstd;
    int wid = t >> 5;
    if ((t & 31) == 0) { ss[wid] = s; sq[wid] = q; }
    __syncthreads();
    if (t == 0) {
        float S = ss[0] + ss[1] + ss[2] + ss[3];
        float Q = sq[0] + sq[1] + sq[2] + sq[3];
        float mean = S * (1.0f / DD);
        float var  = Q * (1.0f / DD) - mean * mean;
        smean = mean;
        srstd = rsqrtf(var + 1e-5f);
    }
    __syncthreads();
    float mean = smean, rstd = srstd;
    float4 wv = ((const float4*)w)[t];
    float4 bv = ((const float4*)bb)[t];
    float4 o;
    o.x = (v.x - mean) * rstd * wv.x + bv.x;
    o.y = (v.y - mean) * rstd * wv.y + bv.y;
    o.z = (v.z - mean) * rstd * wv.z + bv.z;
    o.w = (v.w - mean) * rstd * wv.w + bv.w;
    ((float4*)(y + (size_t)row * DD))[t] = o;
}

// ---------------- sliding-window attention (win=±5) -------------------------
// 1 block per (b,t); warp h handles head h; 2 hd-elements per lane.
__global__ void attn_kernel(const float* __restrict__ qkv,
                            const unsigned char* __restrict__ pad,
                            float* __restrict__ out) {
    int row = blockIdx.x;                // b*T + t
    int b = row / TT, t = row - b * TT;
    int h = threadIdx.x >> 5;
    int lane = threadIdx.x & 31;
    const float scale = 0.125f;          // 1/sqrt(64)
    size_t qoff = (size_t)row * (3 * DD) + h * HDIM + lane * 2;
    float q0 = qkv[qoff]     * scale;
    float q1 = qkv[qoff + 1] * scale;
    float sc[11];
    float mx = -3.0e38f;
#pragma unroll
    for (int jj = 0; jj < 11; jj++) {
        int j = t - 5 + jj;
        float d = -3.0e38f;
        if (j >= 0 && j < TT) {          // uniform across warp
            size_t ko = ((size_t)(b * TT + j)) * (3 * DD) + DD + h * HDIM + lane * 2;
            float dd = q0 * qkv[ko] + q1 * qkv[ko + 1];
#pragma unroll
            for (int o = 16; o > 0; o >>= 1)
                dd += __shfl_xor_sync(0xffffffffu, dd, o);
            if (pad[b * TT + j]) dd += -1e9f;
            d = dd;
        }
        sc[jj] = d;
        mx = fmaxf(mx, d);
    }
    float sum = 0.f;
#pragma unroll
    for (int jj = 0; jj < 11; jj++) {
        float e = (sc[jj] > -1.0e37f) ? expf(sc[jj] - mx) : 0.f;
        sc[jj] = e;
        sum += e;
    }
    float inv = 1.0f / sum;
    float o0 = 0.f, o1 = 0.f;
#pragma unroll
    for (int jj = 0; jj < 11; jj++) {
        int j = t - 5 + jj;
        if (j >= 0 && j < TT) {
            size_t vo = ((size_t)(b * TT + j)) * (3 * DD) + 2 * DD + h * HDIM + lane * 2;
            o0 += sc[jj] * qkv[vo];
            o1 += sc[jj] * qkv[vo + 1];
        }
    }
    size_t oo = (size_t)row * DD + h * HDIM + lane * 2;
    out[oo]     = o0 * inv;
    out[oo + 1] = o1 * inv;
}

// ---------------- TF32 GEMM, 3-stage cp.async pipeline, BK=32 ---------------
// C[N,M] = A[N,K] @ W[M,K]^T + epilogue
// EPI bit0 = GELU, bit1 = residual add (stride M==512), bit2 = sinusoidal PE
// Block 128x128, BK=32, 3 stages, ONE __syncthreads per K-tile.
#define BK    32
#define BKP   36                  // padded stride (32+4): conflict-free frags
#define STAGE_F (128 * BKP)       // floats per tile per stage

template <int EPI>
__global__ __launch_bounds__(256)
void gemm_tf32_kernel(const float* __restrict__ A, const float* __restrict__ W,
                      const float* __restrict__ bias, const float* __restrict__ res,
                      float* __restrict__ C, int M, int K) {
    extern __shared__ float sm[];
    float* As = sm;                  // [3][128][BKP]
    float* Bs = sm + 3 * STAGE_F;    // [3][128][BKP]
    int tid  = threadIdx.x;
    int m0   = blockIdx.y * 128;
    int n0   = blockIdx.x * 128;
    int warp = tid >> 5, lane = tid & 31;
    int wm   = (warp & 3) * 32;     // 4 warps along M
    int wn   = (warp >> 2) * 64;    // 2 warps along N
    int gid  = lane >> 2, tg = lane & 3;

    int lrow = tid >> 3;            // 0..31
    int lcg  = (tid & 7) << 2;      // 0,4,...,28
    const float* Aptr = A + (size_t)m0 * K;
    const float* Wptr = W + (size_t)n0 * K;
    const int NT = K / BK;          // K/32 tiles

    auto issue = [&](int kt, int st) {
        int k0 = kt * BK;
        float* as = As + st * STAGE_F;
        float* bs = Bs + st * STAGE_F;
#pragma unroll
        for (int i = 0; i < 4; i++) {
            int r = lrow + i * 32;
            cp_async16(as + r * BKP + lcg, Aptr + (size_t)r * K + k0 + lcg);
            cp_async16(bs + r * BKP + lcg, Wptr + (size_t)r * K + k0 + lcg);
        }
        cp_commit();
    };

    issue(0, 0);
    issue(1, 1);

    float c[2][8][4];
#pragma unroll
    for (int i = 0; i < 2; i++)
#pragma unroll
        for (int j = 0; j < 8; j++)
#pragma unroll
            for (int k = 0; k < 4; k++) c[i][j][k] = 0.f;

    int st = 0;
    for (int kt = 0; kt < NT; kt++) {
        cp_wait<1>();
        __syncthreads();
        // prefetch tile kt+2 into stage (kt+2)%3 == (kt-1)%3 (safe: all threads
        // finished reading that stage in iteration kt-1, proven by the sync).
        if (kt + 2 < NT) {
            int st2 = st + 2; if (st2 >= 3) st2 -= 3;
            issue(kt + 2, st2);
        } else {
            cp_commit();            // empty group keeps wait<1> semantics uniform
        }
        const float* as = As + st * STAGE_F;
        const float* bs = Bs + st * STAGE_F;
#pragma unroll
        for (int ks = 0; ks < 4; ks++) {
            int kk = ks * 8;
            uint32_t a[2][4], bf[8][2];
#pragma unroll
            for (int mm = 0; mm < 2; mm++) {
                int rr = wm + mm * 16;
                a[mm][0] = __float_as_uint(to_tf32(as[(rr + gid) * BKP + kk + tg]));
                a[mm][1] = __float_as_uint(to_tf32(as[(rr + gid + 8) * BKP + kk + tg]));
                a[mm][2] = __float_as_uint(to_tf32(as[(rr + gid) * BKP + kk + tg + 4]));
                a[mm][3] = __float_as_uint(to_tf32(as[(rr + gid + 8) * BKP + kk + tg + 4]));
            }
#pragma unroll
            for (int nn = 0; nn < 8; nn++) {
                int cc = wn + nn * 8;
                bf[nn][0] = __float_as_uint(to_tf32(bs[(cc + gid) * BKP + kk + tg]));
                bf[nn][1] = __float_as_uint(to_tf32(bs[(cc + gid) * BKP + kk + tg + 4]));
            }
#pragma unroll
            for (int mm = 0; mm < 2; mm++)
#pragma unroll
                for (int nn = 0; nn < 8; nn++) {
                    asm volatile(
                        "mma.sync.aligned.m16n8k8.row.col.f32.tf32.tf32.f32 "
                        "{%0,%1,%2,%3}, {%4,%5,%6,%7}, {%8,%9}, {%0,%1,%2,%3};\n"
                        : "+f"(c[mm][nn][0]), "+f"(c[mm][nn][1]),
                          "+f"(c[mm][nn][2]), "+f"(c[mm][nn][3])
                        : "r"(a[mm][0]), "r"(a[mm][1]), "r"(a[mm][2]), "r"(a[mm][3]),
                          "r"(bf[nn][0]), "r"(bf[nn][1]));
                }
        }
        if (++st == 3) st = 0;
    }
    // ---- epilogue ----
#pragma unroll
    for (int mm = 0; mm < 2; mm++) {
#pragma unroll
        for (int nn = 0; nn < 8; nn++) {
            int r0  = m0 + wm + mm * 16 + gid;
            int col = n0 + wn + nn * 8 + tg * 2;   // always even
#pragma unroll
            for (int half = 0; half < 2; half++) {
                int r = r0 + half * 8;
                float v0 = c[mm][nn][half * 2 + 0] + bias[col];
                float v1 = c[mm][nn][half * 2 + 1] + bias[col + 1];
                if (EPI & 1) { v0 = gelu_f(v0); v1 = gelu_f(v1); }
                if (EPI & 2) {
                    v0 += res[(size_t)r * M + col];
                    v1 += res[(size_t)r * M + col + 1];
                }
                if (EPI & 4) {
                    int tpos = r % TT;
                    float div = expf((float)col * (-9.210340371976184f / 512.0f));
                    float ang = (float)tpos * div;
                    v0 += sinf(ang);   // even col
                    v1 += cosf(ang);   // odd col
                }
                C[(size_t)r * M + col]     = v0;
                C[(size_t)r * M + col + 1] = v1;
            }
        }
    }
}

#define GEMM_SMEM (6 * STAGE_F * (int)sizeof(float))   // 110592 bytes

// ---------------- driver ----------------------------------------------------
extern "C" void kernel_launch(void* const* d_in, const int* in_sizes, int n_in,
                              void* d_out, int out_size) {
    const float* x_in = (const float*)d_in[0];
    const float* dw_w = (const float*)d_in[1];
    const float* dw_b = (const float*)d_in[2];
    const float* pw_w = (const float*)d_in[3];
    const float* pw_b = (const float*)d_in[4];
    const float* Wqkv = (const float*)d_in[5];
    const float* bqkv = (const float*)d_in[6];
    const float* Wo   = (const float*)d_in[7];
    const float* bo   = (const float*)d_in[8];
    const float* ln1w = (const float*)d_in[9];
    const float* ln1b = (const float*)d_in[10];
    const float* ln2w = (const float*)d_in[11];
    const float* ln2b = (const float*)d_in[12];
    const float* W1   = (const float*)d_in[13];
    const float* b1   = (const float*)d_in[14];
    const float* W2   = (const float*)d_in[15];
    const float* b2   = (const float*)d_in[16];
    const unsigned char* pad = (const unsigned char*)d_in[17];

    float *hbuf, *xbuf, *ybuf, *qkvbuf, *attnbuf, *ffnbuf;
    cudaGetSymbolAddress((void**)&hbuf,    g_h);
    cudaGetSymbolAddress((void**)&xbuf,    g_x);
    cudaGetSymbolAddress((void**)&ybuf,    g_y);
    cudaGetSymbolAddress((void**)&qkvbuf,  g_qkv);
    cudaGetSymbolAddress((void**)&attnbuf, g_attn);
    cudaGetSymbolAddress((void**)&ffnbuf,  g_ffn);

    // dynamic-smem opt-in (idempotent, non-stream API; safe under capture)
    cudaFuncSetAttribute(gemm_tf32_kernel<0>, cudaFuncAttributeMaxDynamicSharedMemorySize, GEMM_SMEM);
    cudaFuncSetAttribute(gemm_tf32_kernel<1>, cudaFuncAttributeMaxDynamicSharedMemorySize, GEMM_SMEM);
    cudaFuncSetAttribute(gemm_tf32_kernel<2>, cudaFuncAttributeMaxDynamicSharedMemorySize, GEMM_SMEM);
    cudaFuncSetAttribute(gemm_tf32_kernel<7>, cudaFuncAttributeMaxDynamicSharedMemorySize, GEMM_SMEM);

    // conv block: depthwise -> pointwise GEMM (+bias,GELU,residual,PE)
    conv_dw_kernel<<<NROWS * 128 / 256, 256>>>(x_in, dw_w, dw_b, hbuf);
    gemm_tf32_kernel<7><<<dim3(4, 96), 256, GEMM_SMEM>>>(hbuf, pw_w, pw_b, x_in, xbuf, 512, 512);

    for (int l = 0; l < 4; l++) {
        ln_kernel<<<NROWS, 128>>>(xbuf, ln1w + l * 512, ln1b + l * 512, ybuf);
        gemm_tf32_kernel<0><<<dim3(12, 96), 256, GEMM_SMEM>>>(
            ybuf, Wqkv + (size_t)l * 1536 * 512, bqkv + l * 1536, nullptr,
            qkvbuf, 1536, 512);
        attn_kernel<<<NROWS, 256>>>(qkvbuf, pad, attnbuf);
        gemm_tf32_kernel<2><<<dim3(4, 96), 256, GEMM_SMEM>>>(
            attnbuf, Wo + (size_t)l * 512 * 512, bo + l * 512, xbuf,
            xbuf, 512, 512);
        ln_kernel<<<NROWS, 128>>>(xbuf, ln2w + l * 512, ln2b + l * 512, ybuf);
        gemm_tf32_kernel<1><<<dim3(16, 96), 256, GEMM_SMEM>>>(
            ybuf, W1 + (size_t)l * 2048 * 512, b1 + l * 2048, nullptr,
            ffnbuf, 2048, 512);
        float* dst = (l == 3) ? (float*)d_out : xbuf;
        gemm_tf32_kernel<2><<<dim3(4, 96), 256, GEMM_SMEM>>>(
            ffnbuf, W2 + (size_t)l * 512 * 2048, b2 + l * 512, xbuf,
            dst, 512, 2048);
    }
}

// round 11
// speedup vs baseline: 1.0135x; 1.0135x over previous
#include <cuda_runtime.h>
#include <math.h>
#include <stdint.h>

#define NROWS 12288          // B*T
#define TT    1536
#define DD    512
#define NH    8
#define HDIM  64

// ---------------- scratch (device globals; no allocations allowed) ----------
__device__ float g_h[NROWS * DD];        // conv intermediate
__device__ float g_x[NROWS * DD];        // residual stream
__device__ float g_y[NROWS * DD];        // LN output
__device__ float g_qkv[NROWS * 3 * DD];
__device__ float g_attn[NROWS * DD];
__device__ float g_ffn[NROWS * 4 * DD];

__device__ __forceinline__ float to_tf32(float x) {
    float r;
    asm("cvt.rna.tf32.f32 %0, %1;" : "=f"(r) : "f"(x));
    return r;
}
__device__ __forceinline__ float gelu_f(float v) {
    return 0.5f * v * (1.0f + erff(v * 0.7071067811865476f));
}
__device__ __forceinline__ unsigned smem_u32(const void* p) {
    return (unsigned)__cvta_generic_to_shared(p);
}
__device__ __forceinline__ void cp_async16(void* dst, const void* src) {
    asm volatile("cp.async.cg.shared.global [%0], [%1], 16;\n"
                 :: "r"(smem_u32(dst)), "l"(src));
}
__device__ __forceinline__ void cp_commit() {
    asm volatile("cp.async.commit_group;\n");
}
template <int N>
__device__ __forceinline__ void cp_wait() {
    asm volatile("cp.async.wait_group %0;\n" :: "n"(N));
}

// ---------------- depthwise conv k=5, pad=2 ---------------------------------
__global__ void conv_dw_kernel(const float* __restrict__ x,
                               const float* __restrict__ dww,
                               const float* __restrict__ dwb,
                               float* __restrict__ h) {
    int idx = blockIdx.x * blockDim.x + threadIdx.x;   // over NROWS*128
    int row = idx >> 7;
    int c   = (idx & 127) << 2;
    int b = row / TT, t = row - b * TT;
    float4 acc = *(const float4*)(dwb + c);
#pragma unroll
    for (int w = 0; w < 5; w++) {
        int tt = t + w - 2;
        if (tt >= 0 && tt < TT) {
            float4 xv = *(const float4*)(x + ((size_t)(b * TT + tt)) * DD + c);
            float4 kv = *(const float4*)(dww + w * DD + c);
            acc.x += xv.x * kv.x; acc.y += xv.y * kv.y;
            acc.z += xv.z * kv.z; acc.w += xv.w * kv.w;
        }
    }
    *(float4*)(h + (size_t)row * DD + c) = acc;
}

// ---------------- layernorm (1 block / row, 128 thr, float4) ----------------
__global__ void ln_kernel(const float* __restrict__ x,
                          const float* __restrict__ w,
                          const float* __restrict__ bb,
                          float* __restrict__ y) {
    int row = blockIdx.x;
    int t = threadIdx.x;                 // 128 threads
    float4 v = ((const float4*)(x + (size_t)row * DD))[t];
    float s = v.x + v.y + v.z + v.w;
    float q = v.x * v.x + v.y * v.y + v.z * v.z + v.w * v.w;
#pragma unroll
    for (int o = 16; o > 0; o >>= 1) {
        s += __shfl_xor_sync(0xffffffffu, s, o);
        q += __shfl_xor_sync(0xffffffffu, q, o);
    }
    __shared__ float ss[4], sq[4];
    __shared__ float smean, srstd;
    int wid = t >> 5;
    if ((t & 31) == 0) { ss[wid] = s; sq[wid] = q; }
    __syncthreads();
    if (t == 0) {
        float S = ss[0] + ss[1] + ss[2] + ss[3];
        float Q = sq[0] + sq[1] + sq[2] + sq[3];
        float mean = S * (1.0f / DD);
        float var  = Q * (1.0f / DD) - mean * mean;
        smean = mean;
        srstd = rsqrtf(var + 1e-5f);
    }
    __syncthreads();
    float mean = smean, rstd = srstd;
    float4 wv = ((const float4*)w)[t];
    float4 bv = ((const float4*)bb)[t];
    float4 o;
    o.x = (v.x - mean) * rstd * wv.x + bv.x;
    o.y = (v.y - mean) * rstd * wv.y + bv.y;
    o.z = (v.z - mean) * rstd * wv.z + bv.z;
    o.w = (v.w - mean) * rstd * wv.w + bv.w;
    ((float4*)(y + (size_t)row * DD))[t] = o;
}

// ---------------- sliding-window attention (win=±5) -------------------------
// 1 block per (b,t); warp h handles head h; 2 hd-elements per lane (float2).
__global__ void attn_kernel(const float* __restrict__ qkv,
                            const unsigned char* __restrict__ pad,
                            float* __restrict__ out) {
    int row = blockIdx.x;                // b*T + t
    int b = row / TT, t = row - b * TT;
    int h = threadIdx.x >> 5;
    int lane = threadIdx.x & 31;
    const float scale = 0.125f;          // 1/sqrt(64)
    size_t qoff = (size_t)row * (3 * DD) + h * HDIM + lane * 2;
    float2 qv = *(const float2*)(qkv + qoff);
    float q0 = qv.x * scale;
    float q1 = qv.y * scale;
    float sc[11];
    float mx = -3.0e38f;
#pragma unroll
    for (int jj = 0; jj < 11; jj++) {
        int j = t - 5 + jj;
        float d = -3.0e38f;
        if (j >= 0 && j < TT) {          // uniform across warp
            size_t ko = ((size_t)(b * TT + j)) * (3 * DD) + DD + h * HDIM + lane * 2;
            float2 kv = *(const float2*)(qkv + ko);
            float dd = q0 * kv.x + q1 * kv.y;
#pragma unroll
            for (int o = 16; o > 0; o >>= 1)
                dd += __shfl_xor_sync(0xffffffffu, dd, o);
            if (pad[b * TT + j]) dd += -1e9f;
            d = dd;
        }
        sc[jj] = d;
        mx = fmaxf(mx, d);
    }
    float sum = 0.f;
#pragma unroll
    for (int jj = 0; jj < 11; jj++) {
        float e = (sc[jj] > -1.0e37f) ? expf(sc[jj] - mx) : 0.f;
        sc[jj] = e;
        sum += e;
    }
    float inv = 1.0f / sum;
    float o0 = 0.f, o1 = 0.f;
#pragma unroll
    for (int jj = 0; jj < 11; jj++) {
        int j = t - 5 + jj;
        if (j >= 0 && j < TT) {
            size_t vo = ((size_t)(b * TT + j)) * (3 * DD) + 2 * DD + h * HDIM + lane * 2;
            float2 vv = *(const float2*)(qkv + vo);
            o0 += sc[jj] * vv.x;
            o1 += sc[jj] * vv.y;
        }
    }
    size_t oo = (size_t)row * DD + h * HDIM + lane * 2;
    *(float2*)(out + oo) = make_float2(o0 * inv, o1 * inv);
}

// ---------------- TF32 GEMM, 3-stage cp.async pipeline, BK=32 ---------------
// C[N,M] = A[N,K] @ W[M,K]^T + epilogue
// EPI bit0 = GELU, bit1 = residual add (stride M==512), bit2 = sinusoidal PE
// Block 128x128, BK=32, 3 stages, ONE __syncthreads per K-tile, 2 CTA/SM.
#define BK    32
#define BKP   36                  // padded stride (32+4): conflict-free frags
#define STAGE_F (128 * BKP)       // floats per tile per stage

template <int EPI>
__global__ __launch_bounds__(256, 2)
void gemm_tf32_kernel(const float* __restrict__ A, const float* __restrict__ W,
                      const float* __restrict__ bias, const float* __restrict__ res,
                      float* __restrict__ C, int M, int K) {
    extern __shared__ float sm[];
    float* As = sm;                  // [3][128][BKP]
    float* Bs = sm + 3 * STAGE_F;    // [3][128][BKP]
    int tid  = threadIdx.x;
    int m0   = blockIdx.y * 128;
    int n0   = blockIdx.x * 128;
    int warp = tid >> 5, lane = tid & 31;
    int wm   = (warp & 3) * 32;     // 4 warps along M
    int wn   = (warp >> 2) * 64;    // 2 warps along N
    int gid  = lane >> 2, tg = lane & 3;

    int lrow = tid >> 3;            // 0..31
    int lcg  = (tid & 7) << 2;      // 0,4,...,28
    const float* Aptr = A + (size_t)m0 * K;
    const float* Wptr = W + (size_t)n0 * K;
    const int NT = K / BK;          // K/32 tiles

    auto issue = [&](int kt, int st) {
        int k0 = kt * BK;
        float* as = As + st * STAGE_F;
        float* bs = Bs + st * STAGE_F;
#pragma unroll
        for (int i = 0; i < 4; i++) {
            int r = lrow + i * 32;
            cp_async16(as + r * BKP + lcg, Aptr + (size_t)r * K + k0 + lcg);
            cp_async16(bs + r * BKP + lcg, Wptr + (size_t)r * K + k0 + lcg);
        }
        cp_commit();
    };

    issue(0, 0);
    issue(1, 1);

    float c[2][8][4];
#pragma unroll
    for (int i = 0; i < 2; i++)
#pragma unroll
        for (int j = 0; j < 8; j++)
#pragma unroll
            for (int k = 0; k < 4; k++) c[i][j][k] = 0.f;

    int st = 0;
    for (int kt = 0; kt < NT; kt++) {
        cp_wait<1>();
        __syncthreads();
        // prefetch tile kt+2 into stage (kt+2)%3 == (kt-1)%3 (safe: all threads
        // finished reading that stage in iteration kt-1, proven by the sync).
        if (kt + 2 < NT) {
            int st2 = st + 2; if (st2 >= 3) st2 -= 3;
            issue(kt + 2, st2);
        } else {
            cp_commit();            // empty group keeps wait<1> semantics uniform
        }
        const float* as = As + st * STAGE_F;
        const float* bs = Bs + st * STAGE_F;
#pragma unroll
        for (int ks = 0; ks < 4; ks++) {
            int kk = ks * 8;
            uint32_t a[2][4];
#pragma unroll
            for (int mm = 0; mm < 2; mm++) {
                int rr = wm + mm * 16;
                a[mm][0] = __float_as_uint(to_tf32(as[(rr + gid) * BKP + kk + tg]));
                a[mm][1] = __float_as_uint(to_tf32(as[(rr + gid + 8) * BKP + kk + tg]));
                a[mm][2] = __float_as_uint(to_tf32(as[(rr + gid) * BKP + kk + tg + 4]));
                a[mm][3] = __float_as_uint(to_tf32(as[(rr + gid + 8) * BKP + kk + tg + 4]));
            }
            // b-fragments loaded per-nn: fewer live registers (2 CTA/SM cap)
#pragma unroll
            for (int nn = 0; nn < 8; nn++) {
                int cc = wn + nn * 8;
                uint32_t b0 = __float_as_uint(to_tf32(bs[(cc + gid) * BKP + kk + tg]));
                uint32_t b1 = __float_as_uint(to_tf32(bs[(cc + gid) * BKP + kk + tg + 4]));
#pragma unroll
                for (int mm = 0; mm < 2; mm++) {
                    asm volatile(
                        "mma.sync.aligned.m16n8k8.row.col.f32.tf32.tf32.f32 "
                        "{%0,%1,%2,%3}, {%4,%5,%6,%7}, {%8,%9}, {%0,%1,%2,%3};\n"
                        : "+f"(c[mm][nn][0]), "+f"(c[mm][nn][1]),
                          "+f"(c[mm][nn][2]), "+f"(c[mm][nn][3])
                        : "r"(a[mm][0]), "r"(a[mm][1]), "r"(a[mm][2]), "r"(a[mm][3]),
                          "r"(b0), "r"(b1));
                }
            }
        }
        if (++st == 3) st = 0;
    }
    // ---- epilogue ----
#pragma unroll
    for (int mm = 0; mm < 2; mm++) {
#pragma unroll
        for (int nn = 0; nn < 8; nn++) {
            int r0  = m0 + wm + mm * 16 + gid;
            int col = n0 + wn + nn * 8 + tg * 2;   // always even
#pragma unroll
            for (int half = 0; half < 2; half++) {
                int r = r0 + half * 8;
                float v0 = c[mm][nn][half * 2 + 0] + bias[col];
                float v1 = c[mm][nn][half * 2 + 1] + bias[col + 1];
                if (EPI & 1) { v0 = gelu_f(v0); v1 = gelu_f(v1); }
                if (EPI & 2) {
                    v0 += res[(size_t)r * M + col];
                    v1 += res[(size_t)r * M + col + 1];
                }
                if (EPI & 4) {
                    int tpos = r % TT;
                    float div = expf((float)col * (-9.210340371976184f / 512.0f));
                    float sv, cv;
                    sincosf((float)tpos * div, &sv, &cv);
                    v0 += sv;          // even col
                    v1 += cv;          // odd col
                }
                C[(size_t)r * M + col]     = v0;
                C[(size_t)r * M + col + 1] = v1;
            }
        }
    }
}

#define GEMM_SMEM (6 * STAGE_F * (int)sizeof(float))   // 110592 bytes

// ---------------- driver ----------------------------------------------------
extern "C" void kernel_launch(void* const* d_in, const int* in_sizes, int n_in,
                              void* d_out, int out_size) {
    const float* x_in = (const float*)d_in[0];
    const float* dw_w = (const float*)d_in[1];
    const float* dw_b = (const float*)d_in[2];
    const float* pw_w = (const float*)d_in[3];
    const float* pw_b = (const float*)d_in[4];
    const float* Wqkv = (const float*)d_in[5];
    const float* bqkv = (const float*)d_in[6];
    const float* Wo   = (const float*)d_in[7];
    const float* bo   = (const float*)d_in[8];
    const float* ln1w = (const float*)d_in[9];
    const float* ln1b = (const float*)d_in[10];
    const float* ln2w = (const float*)d_in[11];
    const float* ln2b = (const float*)d_in[12];
    const float* W1   = (const float*)d_in[13];
    const float* b1   = (const float*)d_in[14];
    const float* W2   = (const float*)d_in[15];
    const float* b2   = (const float*)d_in[16];
    const unsigned char* pad = (const unsigned char*)d_in[17];

    float *hbuf, *xbuf, *ybuf, *qkvbuf, *attnbuf, *ffnbuf;
    cudaGetSymbolAddress((void**)&hbuf,    g_h);
    cudaGetSymbolAddress((void**)&xbuf,    g_x);
    cudaGetSymbolAddress((void**)&ybuf,    g_y);
    cudaGetSymbolAddress((void**)&qkvbuf,  g_qkv);
    cudaGetSymbolAddress((void**)&attnbuf, g_attn);
    cudaGetSymbolAddress((void**)&ffnbuf,  g_ffn);

    // dynamic-smem opt-in (idempotent, non-stream API; safe under capture)
    cudaFuncSetAttribute(gemm_tf32_kernel<0>, cudaFuncAttributeMaxDynamicSharedMemorySize, GEMM_SMEM);
    cudaFuncSetAttribute(gemm_tf32_kernel<1>, cudaFuncAttributeMaxDynamicSharedMemorySize, GEMM_SMEM);
    cudaFuncSetAttribute(gemm_tf32_kernel<2>, cudaFuncAttributeMaxDynamicSharedMemorySize, GEMM_SMEM);
    cudaFuncSetAttribute(gemm_tf32_kernel<7>, cudaFuncAttributeMaxDynamicSharedMemorySize, GEMM_SMEM);

    // conv block: depthwise -> pointwise GEMM (+bias,GELU,residual,PE)
    conv_dw_kernel<<<NROWS * 128 / 256, 256>>>(x_in, dw_w, dw_b, hbuf);
    gemm_tf32_kernel<7><<<dim3(4, 96), 256, GEMM_SMEM>>>(hbuf, pw_w, pw_b, x_in, xbuf, 512, 512);

    for (int l = 0; l < 4; l++) {
        ln_kernel<<<NROWS, 128>>>(xbuf, ln1w + l * 512, ln1b + l * 512, ybuf);
        gemm_tf32_kernel<0><<<dim3(12, 96), 256, GEMM_SMEM>>>(
            ybuf, Wqkv + (size_t)l * 1536 * 512, bqkv + l * 1536, nullptr,
            qkvbuf, 1536, 512);
        attn_kernel<<<NROWS, 256>>>(qkvbuf, pad, attnbuf);
        gemm_tf32_kernel<2><<<dim3(4, 96), 256, GEMM_SMEM>>>(
            attnbuf, Wo + (size_t)l * 512 * 512, bo + l * 512, xbuf,
            xbuf, 512, 512);
        ln_kernel<<<NROWS, 128>>>(xbuf, ln2w + l * 512, ln2b + l * 512, ybuf);
        gemm_tf32_kernel<1><<<dim3(16, 96), 256, GEMM_SMEM>>>(
            ybuf, W1 + (size_t)l * 2048 * 512, b1 + l * 2048, nullptr,
            ffnbuf, 2048, 512);
        float* dst = (l == 3) ? (float*)d_out : xbuf;
        gemm_tf32_kernel<2><<<dim3(4, 96), 256, GEMM_SMEM>>>(
            ffnbuf, W2 + (size_t)l * 512 * 2048, b2 + l * 512, xbuf,
            dst, 512, 2048);
    }
}